// round 14
// baseline (speedup 1.0000x reference)
#include <cuda_runtime.h>
#include <cuda_fp16.h>
#include <math.h>

#define BB    128
#define TT    2048
#define KD    128
#define VD    128
#define HD    300
#define ED    400
#define NV    33
#define G4    1200
#define SOS   5
#define STEPS 500
#define NTHR  1024
#define CLU   4
#define TRB   256    // value-transpose blocks
#define KTB   4096   // key-transpose tile blocks
#define WQB   64     // weight-pack blocks
#define NK    428    // gemm k-dim
#define STG   65536  // TMA stage bytes
#define RING_OFF 16
#define SMEM_BYTES 170496

// ---------------- persistent device data (read-only after init) ----------
__device__ float4 g_geq[NV * HD];          // [char][n] = (i,f,g,o) emb-part+biases
__device__ float4 g_wf[NK * HD];           // [k][n] fp32 gate quad (i,f,g,o)
// fp16 copies: keys [b][k][t] (t-minor), values [b][t][v] (v-minor)
__device__ uint4 g_keys4[(size_t)BB * KD * (TT / 8)];
__device__ uint4 g_vals4[(size_t)BB * TT * (VD / 8)];

union U4 { uint4 u; __half2 h[4]; };

__device__ __forceinline__ float sigf(float x) { return 1.f / (1.f + __expf(-x)); }
__device__ __forceinline__ float tanf_(float x) { return 2.f / (1.f + __expf(-2.f * x)) - 1.f; }

// ---------------- smem/cluster/TMA helpers ----------------
__device__ __forceinline__ unsigned smem_u32(const void* p) {
    unsigned a;
    asm("{ .reg .u64 t; cvta.to.shared.u64 t, %1; cvt.u32.u64 %0, t; }"
        : "=r"(a) : "l"(p));
    return a;
}
__device__ __forceinline__ unsigned mapa_rank(unsigned a, unsigned r) {
    unsigned d;
    asm("mapa.shared::cluster.u32 %0, %1, %2;" : "=r"(d) : "r"(a), "r"(r));
    return d;
}
__device__ __forceinline__ float ldsc_f(unsigned a) {
    float v; asm volatile("ld.shared::cluster.f32 %0, [%1];" : "=f"(v) : "r"(a)); return v;
}
__device__ __forceinline__ int ldsc_i(unsigned a) {
    int v; asm volatile("ld.shared::cluster.s32 %0, [%1];" : "=r"(v) : "r"(a)); return v;
}
__device__ __forceinline__ void stsc_f(unsigned a, float v) {
    asm volatile("st.shared::cluster.f32 [%0], %1;" :: "r"(a), "f"(v));
}
#define CLUSTER_SYNC() do { \
    asm volatile("barrier.cluster.arrive.aligned;" ::: "memory"); \
    asm volatile("barrier.cluster.wait.aligned;" ::: "memory"); \
} while (0)

__device__ __forceinline__ void mbar_init(unsigned a, unsigned cnt) {
    asm volatile("mbarrier.init.shared.b64 [%0], %1;" :: "r"(a), "r"(cnt) : "memory");
}
__device__ __forceinline__ void mbar_expect_tx(unsigned a, unsigned bytes) {
    asm volatile("mbarrier.arrive.expect_tx.shared.b64 _, [%0], %1;"
                 :: "r"(a), "r"(bytes) : "memory");
}
__device__ __forceinline__ void tma_ld(unsigned dst, const void* src,
                                       unsigned bytes, unsigned mbar) {
    asm volatile("cp.async.bulk.shared::cluster.global.mbarrier::complete_tx::bytes "
                 "[%0], [%1], %2, [%3];"
                 :: "r"(dst), "l"(src), "r"(bytes), "r"(mbar) : "memory");
}
__device__ __forceinline__ void mbar_wait(unsigned mbar, int parity) {
    asm volatile(
        "{\n\t.reg .pred P;\n\t"
        "WL_%=:\n\t"
        "mbarrier.try_wait.parity.acquire.cta.shared::cta.b64 P, [%0], %1, 0x989680;\n\t"
        "@P bra.uni WD_%=;\n\t"
        "bra.uni WL_%=;\n\t"
        "WD_%=:\n\t}"
        :: "r"(mbar), "r"((unsigned)parity) : "memory");
}

// ---------------- init: precompute + transposes + fp32 weight pack -------
__global__ void init_kernel(const float* __restrict__ keys,
                            const float* __restrict__ values,
                            const float* __restrict__ emb,
                            const float* __restrict__ W_ih,
                            const float* __restrict__ b_ih,
                            const float* __restrict__ b_hh,
                            const float* __restrict__ W_hh) {
    int blk = blockIdx.x, tid = threadIdx.x;
    __shared__ float e_s[ED];
    __shared__ __half hk[KD * 64];

    if (blk < NV) {
        for (int i = tid; i < ED; i += blockDim.x) e_s[i] = emb[blk * ED + i];
        __syncthreads();
        int wid = tid >> 5, lane = tid & 31;
        for (int j = wid; j < G4; j += 8) {
            float acc = 0.f;
            const float* wr = W_ih + (size_t)j * 528;
            for (int k = lane; k < ED; k += 32) acc += e_s[k] * wr[k];
            #pragma unroll
            for (int o = 16; o; o >>= 1) acc += __shfl_xor_sync(0xffffffffu, acc, o);
            if (lane == 0) {
                int g = j / 300, n = j % 300;
                ((float*)&g_geq[blk * HD + n])[g] = acc + b_ih[j] + b_hh[j];
            }
        }
    } else if (blk < NV + TRB) {
        const int CH = TT * BB * VD / 8;
        int xb = blk - NV;
        for (int c = xb * blockDim.x + tid; c < CH; c += TRB * blockDim.x) {
            const float4* src = (const float4*)values + (size_t)c * 2;
            float4 a = src[0], b4 = src[1];
            U4 o;
            o.h[0] = __floats2half2_rn(a.x, a.y);
            o.h[1] = __floats2half2_rn(a.z, a.w);
            o.h[2] = __floats2half2_rn(b4.x, b4.y);
            o.h[3] = __floats2half2_rn(b4.z, b4.w);
            int kc = c & 15;
            int b  = (c >> 4) & 127;
            int t  = c >> 11;
            g_vals4[((size_t)b * TT + t) * 16 + kc] = o.u;
        }
    } else if (blk < NV + TRB + KTB) {
        int bk = blk - (NV + TRB);
        int b  = bk >> 5;
        int tt = (bk & 31) * 64;
        for (int idx = tid; idx < 64 * 32; idx += 256) {
            int t = idx >> 5, k4 = idx & 31;
            float4 v = __ldg((const float4*)(keys + ((size_t)(tt + t) * BB + b) * KD) + k4);
            int k = k4 * 4;
            hk[(k + 0) * 64 + t] = __float2half_rn(v.x);
            hk[(k + 1) * 64 + t] = __float2half_rn(v.y);
            hk[(k + 2) * 64 + t] = __float2half_rn(v.z);
            hk[(k + 3) * 64 + t] = __float2half_rn(v.w);
        }
        __syncthreads();
        for (int idx = tid; idx < 1024; idx += 256) {
            int k = idx >> 3, l8 = idx & 7;
            uint4 o = ((const uint4*)hk)[k * 8 + l8];
            g_keys4[((size_t)b * KD + k) * 256 + (tt >> 3) + l8] = o;
        }
    } else {
        int xb = blk - (NV + TRB + KTB);
        for (int e = xb * blockDim.x + tid; e < NK * HD; e += WQB * blockDim.x) {
            int k = e / HD, n = e % HD;
            float4 o;
            #pragma unroll
            for (int g = 0; g < 4; g++) {
                int row = g * 300 + n;
                float v = (k < 128) ? W_ih[(size_t)row * 528 + 400 + k]
                                    : W_hh[(size_t)row * 300 + (k - 128)];
                ((float*)&o)[g] = v;
            }
            g_wf[e] = o;
        }
    }
}

// ---------------- persistent kernel: batch/CTA, 4-CTA LSTM split, TMA ----
__global__ void __launch_bounds__(NTHR, 1) __cluster_dims__(CLU, 1, 1)
decoder_persistent(const float* __restrict__ W_phi,
                   const float* __restrict__ b_phi,
                   const float* __restrict__ W_proj,
                   const float* __restrict__ b_proj,
                   const float* __restrict__ h0,
                   const float* __restrict__ c0,
                   float* __restrict__ out, int write_preds) {
    extern __shared__ __align__(16) char dsm[];
    // [0,16): 2 mbarriers; [16, 16+2*STG): TMA ring; then floats
    float* fb    = (float*)(dsm + RING_OFF + 2 * STG);
    float* w_s   = fb;            // 2048
    float* scr   = fb + 2048;     // 4800 (lstm partials / cpart)
    float* s_x   = fb + 6848;     // 432  own [ctx 0:128, h_old 128:428]
    float* s_xa  = fb + 7280;     // 4*432 staged x of all cluster batches
    float* s_h   = fb + 9008;     // 304  own h_new
    float* s_c   = fb + 9312;     // 304  c[4 batches][75 n-slice]
    float* s_q   = fb + 9616;     // 128
    float* s_lg  = fb + 9744;     // 36
    float* s_red = fb + 9780;     // 32
    float* s_bc  = fb + 9812;     // 2
    int*   s_chr = (int*)(fb + 9814);   // [4] staged chars
    int*   s_cho = (int*)(fb + 9818);   // own char

    const int b    = blockIdx.x;
    const int rank = b & (CLU - 1);
    const int tid  = threadIdx.x, wid = tid >> 5, lane = tid & 31;
    const int N0   = rank * 75;

    const unsigned mb0 = smem_u32(dsm);
    const unsigned mb1 = mb0 + 8;
    const unsigned ring0 = smem_u32(dsm + RING_OFF);
    const unsigned a_sx  = smem_u32(s_x);
    const unsigned a_sh  = smem_u32(s_h);
    const unsigned a_cho = smem_u32(s_cho);
    const char* kbase = (const char*)g_keys4 + (size_t)b * 524288;
    const char* vbase = (const char*)g_vals4 + (size_t)b * 524288;

    if (tid == 0) { mbar_init(mb0, 1); mbar_init(mb1, 1); }
    for (int i = tid; i < HD; i += NTHR) s_h[i] = h0[i];
    if (tid < 300) s_c[tid] = c0[N0 + (tid % 75)];
    if (tid == 0) s_cho[0] = SOS;
    __syncthreads();

    // prologue: prefetch key chunks 0,1 for the s=-1 attend
    if (tid == 0) {
        mbar_expect_tx(mb0, STG); tma_ld(ring0,       kbase,       STG, mb0);
        mbar_expect_tx(mb1, STG); tma_ld(ring0 + STG, kbase + STG, STG, mb1);
    }

    int ph0 = 0, ph1 = 0;

    for (int s = -1; s < STEPS; ++s) {
        if (s >= 0) {
            // ---- stage x + chars of all 4 cluster batches (after sync1)
            for (int idx = tid; idx < CLU * 428; idx += NTHR) {
                int i = idx / 428, k = idx - i * 428;
                s_xa[i * 432 + k] = (i == rank) ? s_x[k]
                                                : ldsc_f(mapa_rank(a_sx, i) + k * 4);
            }
            if (tid < CLU)
                s_chr[tid] = (tid == rank) ? s_cho[0]
                                           : ldsc_i(mapa_rank(a_cho, tid));
            __syncthreads();

            // ---- gate GEMM: n-slice [N0,75) for ALL 4 batches, weights in regs
            if (tid < 300) {
                int ks = tid / 75, nl = tid % 75;
                int n = N0 + nl;
                int k0 = ks * 107, k1 = k0 + 107;
                float acc[CLU][4];
                #pragma unroll
                for (int i = 0; i < CLU; i++)
                    #pragma unroll
                    for (int g = 0; g < 4; g++) acc[i][g] = 0.f;
                const float4* wp = g_wf + (size_t)k0 * HD + n;
                #pragma unroll 4
                for (int k = k0; k < k1; k++) {
                    float4 w = __ldg(wp); wp += HD;
                    #pragma unroll
                    for (int i = 0; i < CLU; i++) {
                        float x = s_xa[i * 432 + k];
                        acc[i][0] += x * w.x; acc[i][1] += x * w.y;
                        acc[i][2] += x * w.z; acc[i][3] += x * w.w;
                    }
                }
                #pragma unroll
                for (int i = 0; i < CLU; i++)
                    ((float4*)scr)[(ks * 75 + nl) * 4 + i] =
                        make_float4(acc[i][0], acc[i][1], acc[i][2], acc[i][3]);
            }
            __syncthreads();

            // ---- reduce k-splits + activations; distribute h slices
            if (tid < 300) {
                int nl = tid >> 2, bi = tid & 3;
                int n = N0 + nl;
                float4 p0 = ((const float4*)scr)[(0 * 75 + nl) * 4 + bi];
                float4 p1 = ((const float4*)scr)[(1 * 75 + nl) * 4 + bi];
                float4 p2 = ((const float4*)scr)[(2 * 75 + nl) * 4 + bi];
                float4 p3 = ((const float4*)scr)[(3 * 75 + nl) * 4 + bi];
                float4 ge = g_geq[s_chr[bi] * HD + n];
                float gi = p0.x + p1.x + p2.x + p3.x + ge.x;
                float gf = p0.y + p1.y + p2.y + p3.y + ge.y;
                float gg = p0.z + p1.z + p2.z + p3.z + ge.z;
                float go = p0.w + p1.w + p2.w + p3.w + ge.w;
                float cn = sigf(gf) * s_c[bi * 75 + nl] + sigf(gi) * tanf_(gg);
                float hn = sigf(go) * tanf_(cn);
                s_c[bi * 75 + nl] = cn;
                if (bi == rank) s_h[n] = hn;
                else            stsc_f(mapa_rank(a_sh, bi) + n * 4, hn);
            }
            __syncthreads();
            CLUSTER_SYNC();    // sync2: h_new complete in every CTA

            // ---- logits = [h_new, ctx_old] @ W_proj^T; argmax
            for (int v = wid; v < NV; v += 32) {
                float acc = 0.f;
                const float* wr = W_proj + (size_t)v * 428;
                for (int k = lane; k < 428; k += 32) {
                    float x = (k < HD) ? s_h[k] : s_x[k - HD];
                    acc += x * wr[k];
                }
                #pragma unroll
                for (int o = 16; o; o >>= 1) acc += __shfl_xor_sync(0xffffffffu, acc, o);
                if (lane == 0) s_lg[v] = acc + b_proj[v];
            }
            __syncthreads();
            if (tid < NV) out[(size_t)s * (BB * NV) + b * NV + tid] = s_lg[tid];
            if (tid == 0) {
                int am = 0; float mv = s_lg[0];
                for (int v = 1; v < NV; ++v) if (s_lg[v] > mv) { mv = s_lg[v]; am = v; }
                s_cho[0] = am;
                if (write_preds)
                    out[(size_t)STEPS * BB * NV + (size_t)s * BB + b] = (float)am;
            }
        }
        if (s == STEPS - 1) break;   // final attend's ctx is never consumed

        // ================= attend(h_new) via TMA ring ======================
        for (int q = wid; q < KD; q += 32) {
            float acc = 0.f;
            const float* wr = W_phi + (size_t)q * HD;
            for (int k = lane; k < HD; k += 32) acc += s_h[k] * wr[k];
            #pragma unroll
            for (int o = 16; o; o >>= 1) acc += __shfl_xor_sync(0xffffffffu, acc, o);
            if (lane == 0) s_q[q] = acc + b_phi[q];
        }
        __syncthreads();

        // ---- energy: 8 key chunks (16 k-rows x 4KB); thread owns t=2tid,2tid+1
        float e0 = 0.f, e1 = 0.f;
        for (int c = 0; c < 8; c++) {
            int st = c & 1;
            unsigned mb = st ? mb1 : mb0;
            if (st) { mbar_wait(mb, ph1); ph1 ^= 1; }
            else    { mbar_wait(mb, ph0); ph0 ^= 1; }
            const __half2* buf = (const __half2*)(dsm + RING_OFF + st * STG);
            #pragma unroll
            for (int r = 0; r < 16; r++) {
                float2 kv = __half22float2(buf[r * 1024 + tid]);
                float q = s_q[c * 16 + r];
                e0 += q * kv.x;
                e1 += q * kv.y;
            }
            __syncthreads();
            if (tid == 0) {
                int nx = c + 2;
                unsigned dst = ring0 + st * STG;
                mbar_expect_tx(mb, STG);
                if (nx < 8) tma_ld(dst, kbase + (size_t)nx * STG, STG, mb);
                else        tma_ld(dst, vbase + (size_t)(nx - 8) * STG, STG, mb);
            }
        }

        // ---- softmax over per-thread (e0,e1)
        {
            float m = fmaxf(e0, e1);
            #pragma unroll
            for (int o = 16; o; o >>= 1) m = fmaxf(m, __shfl_xor_sync(0xffffffffu, m, o));
            if (lane == 0) s_red[wid] = m;
        }
        __syncthreads();
        if (wid == 0) {
            float v = s_red[lane];
            #pragma unroll
            for (int o = 16; o; o >>= 1) v = fmaxf(v, __shfl_xor_sync(0xffffffffu, v, o));
            if (lane == 0) s_bc[0] = v;
        }
        __syncthreads();
        {
            float M = s_bc[0];
            float w0 = __expf(e0 - M), w1 = __expf(e1 - M);
            ((float2*)w_s)[tid] = make_float2(w0, w1);
            float ls = w0 + w1;
            #pragma unroll
            for (int o = 16; o; o >>= 1) ls += __shfl_xor_sync(0xffffffffu, ls, o);
            if (lane == 0) s_red[wid] = ls;
        }
        __syncthreads();
        if (wid == 0) {
            float v = s_red[lane];
            #pragma unroll
            for (int o = 16; o; o >>= 1) v += __shfl_xor_sync(0xffffffffu, v, o);
            if (lane == 0) s_bc[1] = v;
        }
        __syncthreads();

        // ---- values: 8 chunks (256 t-rows x 256B); kc=v-chunk, tg=t-group
        {
            int kc = tid & 15, tg = tid >> 4;
            float va[8];
            #pragma unroll
            for (int j = 0; j < 8; j++) va[j] = 0.f;
            for (int c = 0; c < 8; c++) {
                int st = c & 1;
                unsigned mb = st ? mb1 : mb0;
                if (st) { mbar_wait(mb, ph1); ph1 ^= 1; }
                else    { mbar_wait(mb, ph0); ph0 ^= 1; }
                const char* buf = dsm + RING_OFF + st * STG;
                #pragma unroll
                for (int j = 0; j < 4; j++) {
                    int row = tg + 64 * j;
                    U4 vv; vv.u = *(const uint4*)(buf + row * 256 + kc * 16);
                    float w = w_s[c * 256 + row];
                    float2 f0 = __half22float2(vv.h[0]);
                    float2 f1 = __half22float2(vv.h[1]);
                    float2 f2 = __half22float2(vv.h[2]);
                    float2 f3 = __half22float2(vv.h[3]);
                    va[0] += w * f0.x; va[1] += w * f0.y;
                    va[2] += w * f1.x; va[3] += w * f1.y;
                    va[4] += w * f2.x; va[5] += w * f2.y;
                    va[6] += w * f3.x; va[7] += w * f3.y;
                }
                __syncthreads();
                if (tid == 0) {
                    int nx = c + 2;
                    unsigned dst = ring0 + st * STG;
                    if (nx < 8) {
                        mbar_expect_tx(mb, STG);
                        tma_ld(dst, vbase + (size_t)nx * STG, STG, mb);
                    } else if (s < STEPS - 2) {     // prefetch next pass keys
                        mbar_expect_tx(mb, STG);
                        tma_ld(dst, kbase + (size_t)(nx - 8) * STG, STG, mb);
                    }
                }
            }
            #pragma unroll
            for (int j = 0; j < 8; j++)
                va[j] += __shfl_xor_sync(0xffffffffu, va[j], 16);
            if ((lane >> 4) == 0) {
                float4* cp = (float4*)(scr + wid * 128 + kc * 8);
                cp[0] = make_float4(va[0], va[1], va[2], va[3]);
                cp[1] = make_float4(va[4], va[5], va[6], va[7]);
            }
        }
        __syncthreads();

        // ctx -> s_x[0:128]; h_new -> s_x[128:428]
        if (tid < 128) {
            float inv = 1.f / s_bc[1];
            float acc = 0.f;
            #pragma unroll
            for (int w = 0; w < 32; w++) acc += scr[w * 128 + tid];
            s_x[tid] = acc * inv;
        }
        for (int i = tid; i < HD; i += NTHR) s_x[128 + i] = s_h[i];
        __syncthreads();
        CLUSTER_SYNC();    // sync1: x + char visible to cluster for next LSTM
    }
}

// ---------------- host launcher ----------------
extern "C" void kernel_launch(void* const* d_in, const int* in_sizes, int n_in,
                              void* d_out, int out_size) {
    const float* keys   = (const float*)d_in[0];
    const float* values = (const float*)d_in[1];
    const float* emb    = (const float*)d_in[2];
    const float* W_phi  = (const float*)d_in[3];
    const float* b_phi  = (const float*)d_in[4];
    const float* W_ih   = (const float*)d_in[5];
    const float* b_ih   = (const float*)d_in[6];
    const float* W_hh   = (const float*)d_in[7];
    const float* b_hh   = (const float*)d_in[8];
    const float* W_proj = (const float*)d_in[9];
    const float* b_proj = (const float*)d_in[10];
    const float* h0     = (const float*)d_in[11];
    const float* c0     = (const float*)d_in[12];
    float* out = (float*)d_out;

    int write_preds = (out_size >= STEPS * BB * NV + STEPS * BB) ? 1 : 0;

    static int attr_done = 0;
    if (!attr_done) {
        cudaFuncSetAttribute(decoder_persistent,
                             cudaFuncAttributeMaxDynamicSharedMemorySize,
                             SMEM_BYTES);
        attr_done = 1;
    }

    init_kernel<<<NV + TRB + KTB + WQB, 256>>>(keys, values, emb, W_ih, b_ih,
                                               b_hh, W_hh);
    decoder_persistent<<<BB, NTHR, SMEM_BYTES>>>(W_phi, b_phi, W_proj, b_proj,
                                                 h0, c0, out, write_preds);
}

// round 15
// speedup vs baseline: 1.0775x; 1.0775x over previous
#include <cuda_runtime.h>
#include <cuda_fp16.h>
#include <math.h>

#define BB    128
#define TT    2048
#define KD    128
#define VD    128
#define HD    300
#define ED    400
#define NV    33
#define G4    1200
#define SOS   5
#define STEPS 500
#define NTHR  1024
#define TRB   256    // value-transpose blocks
#define KTB   4096   // key-transpose tile blocks
#define WQB   64     // weight-pack blocks
#define NK    428    // gemm k-dim
#define NS    5      // pipeline stages
#define CH    32768  // chunk bytes (keys: 8 k-rows; values: 128 t-rows)
#define RING_OFF 128
#define TOTC  (500L * 32)   // total chunks: 500 attends x (16 key + 16 val)
#define SMEM_BYTES 195232

// ---------------- persistent device data (read-only after init) ----------
__device__ float4 g_geq[NV * HD];          // [char][n] = (i,f,g,o) emb-part+biases
__device__ float4 g_wf[NK * HD];           // [k][n] fp32 gate quad (i,f,g,o)
// fp16 copies: keys [b][k][t] (t-minor), values [b][t][v] (v-minor)
__device__ uint4 g_keys4[(size_t)BB * KD * (TT / 8)];
__device__ uint4 g_vals4[(size_t)BB * TT * (VD / 8)];

union U4 { uint4 u; __half2 h[4]; };

__device__ __forceinline__ float sigf(float x) { return 1.f / (1.f + __expf(-x)); }
__device__ __forceinline__ float tanf_(float x) { return 2.f / (1.f + __expf(-2.f * x)) - 1.f; }

// ---------------- smem/cluster/TMA helpers ----------------
__device__ __forceinline__ unsigned smem_u32(const void* p) {
    unsigned a;
    asm("{ .reg .u64 t; cvta.to.shared.u64 t, %1; cvt.u32.u64 %0, t; }"
        : "=r"(a) : "l"(p));
    return a;
}
__device__ __forceinline__ unsigned mapa_rank(unsigned a, unsigned r) {
    unsigned d;
    asm("mapa.shared::cluster.u32 %0, %1, %2;" : "=r"(d) : "r"(a), "r"(r));
    return d;
}
__device__ __forceinline__ float ldsc_f(unsigned a) {
    float v; asm volatile("ld.shared::cluster.f32 %0, [%1];" : "=f"(v) : "r"(a)); return v;
}
__device__ __forceinline__ int ldsc_i(unsigned a) {
    int v; asm volatile("ld.shared::cluster.s32 %0, [%1];" : "=r"(v) : "r"(a)); return v;
}
__device__ __forceinline__ void stsc_f(unsigned a, float v) {
    asm volatile("st.shared::cluster.f32 [%0], %1;" :: "r"(a), "f"(v));
}
#define CLUSTER_SYNC() do { \
    asm volatile("barrier.cluster.arrive.aligned;" ::: "memory"); \
    asm volatile("barrier.cluster.wait.aligned;" ::: "memory"); \
} while (0)

__device__ __forceinline__ void mbar_init(unsigned a, unsigned cnt) {
    asm volatile("mbarrier.init.shared.b64 [%0], %1;" :: "r"(a), "r"(cnt) : "memory");
}
__device__ __forceinline__ void mbar_expect_tx(unsigned a, unsigned bytes) {
    asm volatile("mbarrier.arrive.expect_tx.shared.b64 _, [%0], %1;"
                 :: "r"(a), "r"(bytes) : "memory");
}
__device__ __forceinline__ void mbar_arrive(unsigned a) {
    asm volatile("mbarrier.arrive.shared.b64 _, [%0];" :: "r"(a) : "memory");
}
__device__ __forceinline__ void tma_ld(unsigned dst, const void* src,
                                       unsigned bytes, unsigned mbar) {
    asm volatile("cp.async.bulk.shared::cluster.global.mbarrier::complete_tx::bytes "
                 "[%0], [%1], %2, [%3];"
                 :: "r"(dst), "l"(src), "r"(bytes), "r"(mbar) : "memory");
}
__device__ __forceinline__ void mbar_wait(unsigned mbar, unsigned parity) {
    asm volatile(
        "{\n\t.reg .pred P;\n\t"
        "WL_%=:\n\t"
        "mbarrier.try_wait.parity.acquire.cta.shared::cta.b64 P, [%0], %1, 0x989680;\n\t"
        "@P bra.uni WD_%=;\n\t"
        "bra.uni WL_%=;\n\t"
        "WD_%=:\n\t}"
        :: "r"(mbar), "r"(parity) : "memory");
}

// ---------------- init: precompute + transposes + fp32 weight pack -------
__global__ void init_kernel(const float* __restrict__ keys,
                            const float* __restrict__ values,
                            const float* __restrict__ emb,
                            const float* __restrict__ W_ih,
                            const float* __restrict__ b_ih,
                            const float* __restrict__ b_hh,
                            const float* __restrict__ W_hh) {
    int blk = blockIdx.x, tid = threadIdx.x;
    __shared__ float e_s[ED];
    __shared__ __half hk[KD * 64];

    if (blk < NV) {
        for (int i = tid; i < ED; i += blockDim.x) e_s[i] = emb[blk * ED + i];
        __syncthreads();
        int wid = tid >> 5, lane = tid & 31;
        for (int j = wid; j < G4; j += 8) {
            float acc = 0.f;
            const float* wr = W_ih + (size_t)j * 528;
            for (int k = lane; k < ED; k += 32) acc += e_s[k] * wr[k];
            #pragma unroll
            for (int o = 16; o; o >>= 1) acc += __shfl_xor_sync(0xffffffffu, acc, o);
            if (lane == 0) {
                int g = j / 300, n = j % 300;
                ((float*)&g_geq[blk * HD + n])[g] = acc + b_ih[j] + b_hh[j];
            }
        }
    } else if (blk < NV + TRB) {
        const int CHN = TT * BB * VD / 8;
        int xb = blk - NV;
        for (int c = xb * blockDim.x + tid; c < CHN; c += TRB * blockDim.x) {
            const float4* src = (const float4*)values + (size_t)c * 2;
            float4 a = src[0], b4 = src[1];
            U4 o;
            o.h[0] = __floats2half2_rn(a.x, a.y);
            o.h[1] = __floats2half2_rn(a.z, a.w);
            o.h[2] = __floats2half2_rn(b4.x, b4.y);
            o.h[3] = __floats2half2_rn(b4.z, b4.w);
            int kc = c & 15;
            int b  = (c >> 4) & 127;
            int t  = c >> 11;
            g_vals4[((size_t)b * TT + t) * 16 + kc] = o.u;
        }
    } else if (blk < NV + TRB + KTB) {
        int bk = blk - (NV + TRB);
        int b  = bk >> 5;
        int tt = (bk & 31) * 64;
        for (int idx = tid; idx < 64 * 32; idx += 256) {
            int t = idx >> 5, k4 = idx & 31;
            float4 v = __ldg((const float4*)(keys + ((size_t)(tt + t) * BB + b) * KD) + k4);
            int k = k4 * 4;
            hk[(k + 0) * 64 + t] = __float2half_rn(v.x);
            hk[(k + 1) * 64 + t] = __float2half_rn(v.y);
            hk[(k + 2) * 64 + t] = __float2half_rn(v.z);
            hk[(k + 3) * 64 + t] = __float2half_rn(v.w);
        }
        __syncthreads();
        for (int idx = tid; idx < 1024; idx += 256) {
            int k = idx >> 3, l8 = idx & 7;
            uint4 o = ((const uint4*)hk)[k * 8 + l8];
            g_keys4[((size_t)b * KD + k) * 256 + (tt >> 3) + l8] = o;
        }
    } else {
        int xb = blk - (NV + TRB + KTB);
        for (int e = xb * blockDim.x + tid; e < NK * HD; e += WQB * blockDim.x) {
            int k = e / HD, n = e % HD;
            float4 o;
            #pragma unroll
            for (int g = 0; g < 4; g++) {
                int row = g * 300 + n;
                float v = (k < 128) ? W_ih[(size_t)row * 528 + 400 + k]
                                    : W_hh[(size_t)row * 300 + (k - 128)];
                ((float*)&o)[g] = v;
            }
            g_wf[e] = o;
        }
    }
}

// ---------------- persistent kernel: 5-stage TMA pipeline + 2-CTA LSTM ---
__global__ void __launch_bounds__(NTHR, 1) __cluster_dims__(2, 1, 1)
decoder_persistent(const float* __restrict__ W_phi,
                   const float* __restrict__ b_phi,
                   const float* __restrict__ W_proj,
                   const float* __restrict__ b_proj,
                   const float* __restrict__ h0,
                   const float* __restrict__ c0,
                   float* __restrict__ out, int write_preds) {
    extern __shared__ __align__(16) char dsm[];
    // [0,128): mbarriers (full[5] @0, empty[5] @64); [128, 128+5*CH): ring
    float* fb    = (float*)(dsm + RING_OFF + NS * CH);
    float* w_s   = fb;            // 2048
    float* scr   = fb + 2048;     // 4096 (lstm partials / cpart)
    float* s_x   = fb + 6144;     // 432  [ctx 0:128, h_old 128:428]
    float* s_xp  = fb + 6576;     // 432  partner x copy
    float* s_h   = fb + 7008;     // 304
    float* s_c   = fb + 7312;     // 304  c[2 batches][150 n-slice]
    float* s_q   = fb + 7616;     // 128
    float* s_lg  = fb + 7744;     // 36
    float* s_red = fb + 7780;     // 32
    float* s_bc  = fb + 7812;     // 2
    int*   s_chr = (int*)(fb + 7814); // [0]=own char, [1]=partner char

    const int b    = blockIdx.x;
    const int rank = b & 1;
    const int pr   = rank ^ 1;
    const int tid  = threadIdx.x, wid = tid >> 5, lane = tid & 31;
    const int N0   = rank * 150;

    const unsigned mbF = smem_u32(dsm);          // full[st] = mbF + st*8
    const unsigned mbE = mbF + 64;               // empty[st] = mbE + st*8
    const unsigned ring0 = smem_u32(dsm + RING_OFF);
    const unsigned a_sx  = smem_u32(s_x);
    const unsigned a_sh  = smem_u32(s_h);
    const unsigned a_chr = smem_u32(s_chr);
    const char* kbase = (const char*)g_keys4 + (size_t)b * 524288;
    const char* vbase = (const char*)g_vals4 + (size_t)b * 524288;

    if (tid == 0) {
        #pragma unroll
        for (int i = 0; i < NS; i++) {
            mbar_init(mbF + i * 8, 1);
            mbar_init(mbE + i * 8, 32);
        }
    }
    for (int i = tid; i < HD; i += NTHR) s_h[i] = h0[i];
    if (tid < 300) s_c[tid] = c0[N0 + (tid % 150)];
    if (tid == 0) s_chr[0] = SOS;
    __syncthreads();

    // prologue: fill all 5 stages (chunk c address: idx=c&31; <16 keys, else vals)
    if (tid == 0) {
        #pragma unroll
        for (int c = 0; c < NS; c++) {
            const char* src = (c < 16) ? (kbase + (size_t)c * CH)
                                       : (vbase + (size_t)(c - 16) * CH);
            mbar_expect_tx(mbF + c * 8, CH);
            tma_ld(ring0 + c * CH, src, CH, mbF + c * 8);
        }
    }

    for (int s = -1; s < STEPS; ++s) {
        if (s >= 0) {
            // ---- exchange partner x + char (covered by prev cluster sync)
            {
                unsigned pxa = mapa_rank(a_sx, pr);
                for (int k = tid; k < 428; k += NTHR) s_xp[k] = ldsc_f(pxa + k * 4);
                if (tid == 0) s_chr[1] = ldsc_i(mapa_rank(a_chr, pr));
            }
            __syncthreads();

            // ---- gate GEMM: n-slice [N0,150) for BOTH batches, k-split 3
            if (tid < 900) {
                int ks = tid / 300, r2 = tid % 300;
                int bsel = r2 / 150, nl = r2 % 150;
                int n = N0 + nl;
                const float* xs = bsel ? s_xp : s_x;
                int k0 = ks * 143, k1 = (ks == 2) ? NK : (k0 + 143);
                float a0 = 0.f, a1 = 0.f, a2 = 0.f, a3 = 0.f;
                const float4* wp = g_wf + (size_t)k0 * HD + n;
                #pragma unroll 8
                for (int k = k0; k < k1; k++) {
                    float4 w = __ldg(wp); wp += HD;
                    float x = xs[k];
                    a0 += x * w.x; a1 += x * w.y; a2 += x * w.z; a3 += x * w.w;
                }
                ((float4*)scr)[ks * 300 + r2] = make_float4(a0, a1, a2, a3);
            }
            __syncthreads();

            // ---- reduce + activations; own half local, partner half via DSMEM
            if (tid < 300) {
                int bsel = tid / 150, nl = tid % 150;
                int n = N0 + nl;
                float4 p0 = ((const float4*)scr)[tid];
                float4 p1 = ((const float4*)scr)[300 + tid];
                float4 p2 = ((const float4*)scr)[600 + tid];
                float4 ge = g_geq[s_chr[bsel] * HD + n];
                float gi = p0.x + p1.x + p2.x + ge.x;
                float gf = p0.y + p1.y + p2.y + ge.y;
                float gg = p0.z + p1.z + p2.z + ge.z;
                float go = p0.w + p1.w + p2.w + ge.w;
                float cn = sigf(gf) * s_c[tid] + sigf(gi) * tanf_(gg);
                float hn = sigf(go) * tanf_(cn);
                s_c[tid] = cn;
                if (bsel == 0) s_h[n] = hn;
                else           stsc_f(mapa_rank(a_sh, pr) + n * 4, hn);
            }
            __syncthreads();
            CLUSTER_SYNC();    // h_new complete in both CTAs

            // ---- logits = [h_new, ctx_old] @ W_proj^T; argmax
            for (int v = wid; v < NV; v += 32) {
                float acc = 0.f;
                const float* wr = W_proj + (size_t)v * 428;
                for (int k = lane; k < 428; k += 32) {
                    float x = (k < HD) ? s_h[k] : s_x[k - HD];
                    acc += x * wr[k];
                }
                #pragma unroll
                for (int o = 16; o; o >>= 1) acc += __shfl_xor_sync(0xffffffffu, acc, o);
                if (lane == 0) s_lg[v] = acc + b_proj[v];
            }
            __syncthreads();
            if (tid < NV) out[(size_t)s * (BB * NV) + b * NV + tid] = s_lg[tid];
            if (tid == 0) {
                int am = 0; float mv = s_lg[0];
                for (int v = 1; v < NV; ++v) if (s_lg[v] > mv) { mv = s_lg[v]; am = v; }
                s_chr[0] = am;
                if (write_preds)
                    out[(size_t)STEPS * BB * NV + (size_t)s * BB + b] = (float)am;
            }
        }
        if (s == STEPS - 1) break;   // final attend's ctx is never consumed

        // ================= attend(h_new): pipelined chunk consumption ======
        for (int q = wid; q < KD; q += 32) {
            float acc = 0.f;
            const float* wr = W_phi + (size_t)q * HD;
            for (int k = lane; k < HD; k += 32) acc += s_h[k] * wr[k];
            #pragma unroll
            for (int o = 16; o; o >>= 1) acc += __shfl_xor_sync(0xffffffffu, acc, o);
            if (lane == 0) s_q[q] = acc + b_phi[q];
        }
        __syncthreads();

        const long gbase = (long)(s + 1) * 32;

        // ---- energy: 16 key chunks (8 k-rows x 4KB); NO block syncs
        float e0 = 0.f, e1 = 0.f;
        for (int ci = 0; ci < 16; ci++) {
            long gc = gbase + ci;
            int st = (int)(gc % NS);
            unsigned par = (unsigned)((gc / NS) & 1);
            if (lane == 0) mbar_wait(mbF + st * 8, par);
            __syncwarp();
            const __half2* buf = (const __half2*)(dsm + RING_OFF + st * CH);
            #pragma unroll
            for (int r = 0; r < 8; r++) {
                float2 kv = __half22float2(buf[r * 1024 + tid]);
                float q = s_q[ci * 8 + r];
                e0 += q * kv.x;
                e1 += q * kv.y;
            }
            __syncwarp();
            if (lane == 0) mbar_arrive(mbE + st * 8);
            if (tid == 0) {
                long nc = gc + NS;
                if (nc < TOTC) {
                    mbar_wait(mbE + st * 8, par);   // empty round gc/NS done
                    int idx = (int)(nc & 31);
                    const char* src = (idx < 16) ? (kbase + (size_t)idx * CH)
                                                 : (vbase + (size_t)(idx - 16) * CH);
                    mbar_expect_tx(mbF + st * 8, CH);
                    tma_ld(ring0 + st * CH, src, CH, mbF + st * 8);
                }
            }
        }
        __syncthreads();

        // ---- softmax over per-thread (e0,e1)
        {
            float m = fmaxf(e0, e1);
            #pragma unroll
            for (int o = 16; o; o >>= 1) m = fmaxf(m, __shfl_xor_sync(0xffffffffu, m, o));
            if (lane == 0) s_red[wid] = m;
        }
        __syncthreads();
        if (wid == 0) {
            float v = s_red[lane];
            #pragma unroll
            for (int o = 16; o; o >>= 1) v = fmaxf(v, __shfl_xor_sync(0xffffffffu, v, o));
            if (lane == 0) s_bc[0] = v;
        }
        __syncthreads();
        {
            float M = s_bc[0];
            float w0 = __expf(e0 - M), w1 = __expf(e1 - M);
            ((float2*)w_s)[tid] = make_float2(w0, w1);
            float ls = w0 + w1;
            #pragma unroll
            for (int o = 16; o; o >>= 1) ls += __shfl_xor_sync(0xffffffffu, ls, o);
            if (lane == 0) s_red[wid] = ls;
        }
        __syncthreads();
        if (wid == 0) {
            float v = s_red[lane];
            #pragma unroll
            for (int o = 16; o; o >>= 1) v += __shfl_xor_sync(0xffffffffu, v, o);
            if (lane == 0) s_bc[1] = v;
        }
        __syncthreads();

        // ---- values: 16 chunks (128 t-rows x 256B); NO block syncs in loop
        {
            int kc = tid & 15, tg = tid >> 4;
            float va[8];
            #pragma unroll
            for (int j = 0; j < 8; j++) va[j] = 0.f;
            for (int ci = 0; ci < 16; ci++) {
                long gc = gbase + 16 + ci;
                int st = (int)(gc % NS);
                unsigned par = (unsigned)((gc / NS) & 1);
                if (lane == 0) mbar_wait(mbF + st * 8, par);
                __syncwarp();
                const char* buf = dsm + RING_OFF + st * CH;
                #pragma unroll
                for (int j = 0; j < 2; j++) {
                    int row = tg + 64 * j;
                    U4 vv; vv.u = *(const uint4*)(buf + row * 256 + kc * 16);
                    float w = w_s[ci * 128 + row];
                    float2 f0 = __half22float2(vv.h[0]);
                    float2 f1 = __half22float2(vv.h[1]);
                    float2 f2 = __half22float2(vv.h[2]);
                    float2 f3 = __half22float2(vv.h[3]);
                    va[0] += w * f0.x; va[1] += w * f0.y;
                    va[2] += w * f1.x; va[3] += w * f1.y;
                    va[4] += w * f2.x; va[5] += w * f2.y;
                    va[6] += w * f3.x; va[7] += w * f3.y;
                }
                __syncwarp();
                if (lane == 0) mbar_arrive(mbE + st * 8);
                if (tid == 0) {
                    long nc = gc + NS;
                    if (nc < TOTC) {
                        mbar_wait(mbE + st * 8, par);
                        int idx = (int)(nc & 31);
                        const char* src = (idx < 16) ? (kbase + (size_t)idx * CH)
                                                     : (vbase + (size_t)(idx - 16) * CH);
                        mbar_expect_tx(mbF + st * 8, CH);
                        tma_ld(ring0 + st * CH, src, CH, mbF + st * 8);
                    }
                }
            }
            #pragma unroll
            for (int j = 0; j < 8; j++)
                va[j] += __shfl_xor_sync(0xffffffffu, va[j], 16);
            if ((lane >> 4) == 0) {
                float4* cp = (float4*)(scr + wid * 128 + kc * 8);
                cp[0] = make_float4(va[0], va[1], va[2], va[3]);
                cp[1] = make_float4(va[4], va[5], va[6], va[7]);
            }
        }
        __syncthreads();

        // ctx -> s_x[0:128]; h_new -> s_x[128:428]
        if (tid < 128) {
            float inv = 1.f / s_bc[1];
            float acc = 0.f;
            #pragma unroll
            for (int w = 0; w < 32; w++) acc += scr[w * 128 + tid];
            s_x[tid] = acc * inv;
        }
        for (int i = tid; i < HD; i += NTHR) s_x[128 + i] = s_h[i];
        __syncthreads();
        CLUSTER_SYNC();    // x + char visible to partner for next LSTM
    }
}

// ---------------- host launcher ----------------
extern "C" void kernel_launch(void* const* d_in, const int* in_sizes, int n_in,
                              void* d_out, int out_size) {
    const float* keys   = (const float*)d_in[0];
    const float* values = (const float*)d_in[1];
    const float* emb    = (const float*)d_in[2];
    const float* W_phi  = (const float*)d_in[3];
    const float* b_phi  = (const float*)d_in[4];
    const float* W_ih   = (const float*)d_in[5];
    const float* b_ih   = (const float*)d_in[6];
    const float* W_hh   = (const float*)d_in[7];
    const float* b_hh   = (const float*)d_in[8];
    const float* W_proj = (const float*)d_in[9];
    const float* b_proj = (const float*)d_in[10];
    const float* h0     = (const float*)d_in[11];
    const float* c0     = (const float*)d_in[12];
    float* out = (float*)d_out;

    int write_preds = (out_size >= STEPS * BB * NV + STEPS * BB) ? 1 : 0;

    static int attr_done = 0;
    if (!attr_done) {
        cudaFuncSetAttribute(decoder_persistent,
                             cudaFuncAttributeMaxDynamicSharedMemorySize,
                             SMEM_BYTES);
        attr_done = 1;
    }

    init_kernel<<<NV + TRB + KTB + WQB, 256>>>(keys, values, emb, W_ih, b_ih,
                                               b_hh, W_hh);
    decoder_persistent<<<BB, NTHR, SMEM_BYTES>>>(W_phi, b_phi, W_proj, b_proj,
                                                 h0, c0, out, write_preds);
}

// round 17
// speedup vs baseline: 1.1533x; 1.0704x over previous
#include <cuda_runtime.h>
#include <cuda_fp16.h>
#include <math.h>

#define BB    128
#define TT    2048
#define KD    128
#define VD    128
#define HD    300
#define ED    400
#define NV    33
#define G4    1200
#define SOS   5
#define STEPS 500
#define NTHR  512
#define TRB   256    // value-transpose blocks
#define KTB   4096   // key-transpose tile blocks
#define WQB   64     // weight-pack blocks
#define NK    428    // gemm k-dim
#define NS    5      // pipeline stages
#define CH    16384  // chunk bytes (keys: 8 k-rows x 1024t; values: 64 t-rows)
#define RING_OFF 128
#define CPS   32     // chunks per attend: 16 key + 16 value (256KB+256KB per b2)
#define TOTC  (500L * CPS)
#define BSTRIDE 262144   // bytes per b2 for keys AND values (1024*128*2)
#define SMEM_BYTES 99520

// ---------------- persistent device data (read-only after init) ----------
__device__ float4 g_geq[NV * HD];          // [char][n] = (i,f,g,o) emb-part+biases
__device__ float4 g_wf[NK * HD];           // [k][n] fp32 gate quad (i,f,g,o)
// fp16 copies, t-split: keys [b2][k][t'] (t-minor), values [b2][t'][v]
// where b2 = batch*2 + thalf, t' in [0,1024)
__device__ uint4 g_keys4[(size_t)BB * KD * (TT / 8)];
__device__ uint4 g_vals4[(size_t)BB * TT * (VD / 8)];

union U4 { uint4 u; __half2 h[4]; };

__device__ __forceinline__ float sigf(float x) { return 1.f / (1.f + __expf(-x)); }
__device__ __forceinline__ float tanf_(float x) { return 2.f / (1.f + __expf(-2.f * x)) - 1.f; }

// ---------------- smem/cluster/TMA helpers ----------------
__device__ __forceinline__ unsigned smem_u32(const void* p) {
    unsigned a;
    asm("{ .reg .u64 t; cvta.to.shared.u64 t, %1; cvt.u32.u64 %0, t; }"
        : "=r"(a) : "l"(p));
    return a;
}
__device__ __forceinline__ unsigned mapa_rank(unsigned a, unsigned r) {
    unsigned d;
    asm("mapa.shared::cluster.u32 %0, %1, %2;" : "=r"(d) : "r"(a), "r"(r));
    return d;
}
__device__ __forceinline__ void stsc_f(unsigned a, float v) {
    asm volatile("st.shared::cluster.f32 [%0], %1;" :: "r"(a), "f"(v));
}
#define CLUSTER_SYNC() do { \
    asm volatile("barrier.cluster.arrive.aligned;" ::: "memory"); \
    asm volatile("barrier.cluster.wait.aligned;" ::: "memory"); \
} while (0)

__device__ __forceinline__ void mbar_init(unsigned a, unsigned cnt) {
    asm volatile("mbarrier.init.shared.b64 [%0], %1;" :: "r"(a), "r"(cnt) : "memory");
}
__device__ __forceinline__ void mbar_expect_tx(unsigned a, unsigned bytes) {
    asm volatile("mbarrier.arrive.expect_tx.shared.b64 _, [%0], %1;"
                 :: "r"(a), "r"(bytes) : "memory");
}
__device__ __forceinline__ void mbar_arrive(unsigned a) {
    asm volatile("mbarrier.arrive.shared.b64 _, [%0];" :: "r"(a) : "memory");
}
__device__ __forceinline__ void tma_ld(unsigned dst, const void* src,
                                       unsigned bytes, unsigned mbar) {
    asm volatile("cp.async.bulk.shared::cluster.global.mbarrier::complete_tx::bytes "
                 "[%0], [%1], %2, [%3];"
                 :: "r"(dst), "l"(src), "r"(bytes), "r"(mbar) : "memory");
}
__device__ __forceinline__ void mbar_wait(unsigned mbar, unsigned parity) {
    asm volatile(
        "{\n\t.reg .pred P;\n\t"
        "WL_%=:\n\t"
        "mbarrier.try_wait.parity.acquire.cta.shared::cta.b64 P, [%0], %1, 0x989680;\n\t"
        "@P bra.uni WD_%=;\n\t"
        "bra.uni WL_%=;\n\t"
        "WD_%=:\n\t}"
        :: "r"(mbar), "r"(parity) : "memory");
}

// ---------------- init: precompute + t-split transposes + weight pack ----
__global__ void init_kernel(const float* __restrict__ keys,
                            const float* __restrict__ values,
                            const float* __restrict__ emb,
                            const float* __restrict__ W_ih,
                            const float* __restrict__ b_ih,
                            const float* __restrict__ b_hh,
                            const float* __restrict__ W_hh) {
    int blk = blockIdx.x, tid = threadIdx.x;
    __shared__ float e_s[ED];
    __shared__ __half hk[KD * 64];

    if (blk < NV) {
        for (int i = tid; i < ED; i += blockDim.x) e_s[i] = emb[blk * ED + i];
        __syncthreads();
        int wid = tid >> 5, lane = tid & 31;
        for (int j = wid; j < G4; j += 8) {
            float acc = 0.f;
            const float* wr = W_ih + (size_t)j * 528;
            for (int k = lane; k < ED; k += 32) acc += e_s[k] * wr[k];
            #pragma unroll
            for (int o = 16; o; o >>= 1) acc += __shfl_xor_sync(0xffffffffu, acc, o);
            if (lane == 0) {
                int g = j / 300, n = j % 300;
                ((float*)&g_geq[blk * HD + n])[g] = acc + b_ih[j] + b_hh[j];
            }
        }
    } else if (blk < NV + TRB) {
        // values: [t][b][v] f32 -> [b2][t'][v] f16
        const int CHN = TT * BB * VD / 8;
        int xb = blk - NV;
        for (int c = xb * blockDim.x + tid; c < CHN; c += TRB * blockDim.x) {
            const float4* src = (const float4*)values + (size_t)c * 2;
            float4 a = src[0], b4 = src[1];
            U4 o;
            o.h[0] = __floats2half2_rn(a.x, a.y);
            o.h[1] = __floats2half2_rn(a.z, a.w);
            o.h[2] = __floats2half2_rn(b4.x, b4.y);
            o.h[3] = __floats2half2_rn(b4.z, b4.w);
            int kc = c & 15;
            int b  = (c >> 4) & 127;
            int t  = c >> 11;
            int r  = t >> 10, tp = t & 1023;
            g_vals4[((size_t)(b * 2 + r) * 1024 + tp) * 16 + kc] = o.u;
        }
    } else if (blk < NV + TRB + KTB) {
        // keys: [t][b][k] f32 -> [b2][k][t'] f16 via smem tile (64 t x 128 k)
        int bk = blk - (NV + TRB);
        int b  = bk >> 5;
        int tt = bk & 31;                    // t-tile: t in [tt*64, +64)
        int r  = tt >> 4;
        int tu = (tt & 15) * 8;              // uint4 offset within [k] row
        for (int idx = tid; idx < 64 * 32; idx += 256) {
            int t = idx >> 5, k4 = idx & 31;
            float4 v = __ldg((const float4*)(keys + ((size_t)(tt * 64 + t) * BB + b) * KD) + k4);
            int k = k4 * 4;
            hk[(k + 0) * 64 + t] = __float2half_rn(v.x);
            hk[(k + 1) * 64 + t] = __float2half_rn(v.y);
            hk[(k + 2) * 64 + t] = __float2half_rn(v.z);
            hk[(k + 3) * 64 + t] = __float2half_rn(v.w);
        }
        __syncthreads();
        for (int idx = tid; idx < 1024; idx += 256) {
            int k = idx >> 3, l8 = idx & 7;
            uint4 o = ((const uint4*)hk)[k * 8 + l8];
            g_keys4[((size_t)(b * 2 + r) * 128 + k) * 128 + tu + l8] = o;
        }
    } else {
        int xb = blk - (NV + TRB + KTB);
        for (int e = xb * blockDim.x + tid; e < NK * HD; e += WQB * blockDim.x) {
            int k = e / HD, n = e % HD;
            float4 o;
            #pragma unroll
            for (int g = 0; g < 4; g++) {
                int row = g * 300 + n;
                float v = (k < 128) ? W_ih[(size_t)row * 528 + 400 + k]
                                    : W_hh[(size_t)row * 300 + (k - 128)];
                ((float*)&o)[g] = v;
            }
            g_wf[e] = o;
        }
    }
}

// ------- persistent kernel: one batch per 2-CTA cluster (t-split) --------
__global__ void __launch_bounds__(NTHR, 2) __cluster_dims__(2, 1, 1)
decoder_persistent(const float* __restrict__ W_phi,
                   const float* __restrict__ b_phi,
                   const float* __restrict__ W_proj,
                   const float* __restrict__ b_proj,
                   const float* __restrict__ h0,
                   const float* __restrict__ c0,
                   float* __restrict__ out, int write_preds) {
    extern __shared__ __align__(16) char dsm[];
    float* fb    = (float*)(dsm + RING_OFF + NS * CH);
    float* w_s   = fb;            // 1024 local weights (own 1024 t)
    float* scr   = fb + 1024;     // 2048 (lstm partials / cpart)
    float* s_x   = fb + 3072;     // 432  [ctx 0:128, h_old 128:428]
    float* s_h   = fb + 3504;     // 304
    float* s_c   = fb + 3808;     // 152  own n-slice c
    float* s_q   = fb + 3960;     // 128
    float* s_lg  = fb + 4088;     // 36
    float* s_red = fb + 4124;     // 16
    float* s_ms  = fb + 4140;     // [0]=m_own [1]=s_own [2]=m_peer [3]=s_peer
    float* s_cxp = fb + 4144;     // 128 peer ctx partial
    int*   s_chr = (int*)(fb + 4272);

    const int b2   = blockIdx.x;          // (batch, thalf)
    const int b    = b2 >> 1;
    const int rank = b2 & 1;
    const int pr   = rank ^ 1;
    const int tid  = threadIdx.x, wid = tid >> 5, lane = tid & 31;
    const int N0   = rank * 150;

    const unsigned mbF = smem_u32(dsm);
    const unsigned mbE = mbF + 64;
    const unsigned ring0 = smem_u32(dsm + RING_OFF);
    const unsigned a_sh  = smem_u32(s_h);
    const unsigned a_ms  = smem_u32(s_ms);
    const unsigned a_cxp = smem_u32(s_cxp);
    const char* kbase = (const char*)g_keys4 + (size_t)b2 * BSTRIDE;
    const char* vbase = (const char*)g_vals4 + (size_t)b2 * BSTRIDE;

    if (tid == 0) {
        #pragma unroll
        for (int i = 0; i < NS; i++) {
            mbar_init(mbF + i * 8, 1);
            mbar_init(mbE + i * 8, 16);
        }
    }
    for (int i = tid; i < HD; i += NTHR) s_h[i] = h0[i];
    if (tid < 150) s_c[tid] = c0[N0 + tid];
    if (tid == 0) s_chr[0] = SOS;
    __syncthreads();

    // prologue: fill NS stages (chunk idx<16 -> keys, else values)
    if (tid == 0) {
        #pragma unroll
        for (int c = 0; c < NS; c++) {
            const char* src = (c < 16) ? (kbase + (size_t)c * CH)
                                       : (vbase + (size_t)(c - 16) * CH);
            mbar_expect_tx(mbF + c * 8, CH);
            tma_ld(ring0 + c * CH, src, CH, mbF + c * 8);
        }
    }

    for (int s = -1; s < STEPS; ++s) {
        if (s >= 0) {
            // ---- gate GEMM: n-slice [N0,150) for own batch, k-split 3
            if (tid < 450) {
                int ks = tid / 150, nl = tid % 150;
                int n = N0 + nl;
                int k0 = ks * 143, k1 = (ks == 2) ? NK : (k0 + 143);
                float a0 = 0.f, a1 = 0.f, a2 = 0.f, a3 = 0.f;
                const float4* wp = g_wf + (size_t)k0 * HD + n;
                #pragma unroll 8
                for (int k = k0; k < k1; k++) {
                    float4 w = __ldg(wp); wp += HD;
                    float x = s_x[k];
                    a0 += x * w.x; a1 += x * w.y; a2 += x * w.z; a3 += x * w.w;
                }
                ((float4*)scr)[ks * 150 + nl] = make_float4(a0, a1, a2, a3);
            }
            __syncthreads();

            // ---- reduce + activations; own half local, peer half via DSMEM
            if (tid < 150) {
                int n = N0 + tid;
                float4 p0 = ((const float4*)scr)[tid];
                float4 p1 = ((const float4*)scr)[150 + tid];
                float4 p2 = ((const float4*)scr)[300 + tid];
                float4 ge = g_geq[s_chr[0] * HD + n];
                float gi = p0.x + p1.x + p2.x + ge.x;
                float gf = p0.y + p1.y + p2.y + ge.y;
                float gg = p0.z + p1.z + p2.z + ge.z;
                float go = p0.w + p1.w + p2.w + ge.w;
                float cn = sigf(gf) * s_c[tid] + sigf(gi) * tanf_(gg);
                float hn = sigf(go) * tanf_(cn);
                s_c[tid] = cn;
                s_h[n] = hn;
                stsc_f(mapa_rank(a_sh, pr) + n * 4, hn);
            }
            __syncthreads();
            CLUSTER_SYNC();    // (1) full h_new visible in both CTAs

            // ---- logits (both CTAs compute identically); argmax -> char
            for (int v = wid; v < NV; v += 16) {
                float acc = 0.f;
                const float* wr = W_proj + (size_t)v * 428;
                for (int k = lane; k < 428; k += 32) {
                    float x = (k < HD) ? s_h[k] : s_x[k - HD];
                    acc += x * wr[k];
                }
                #pragma unroll
                for (int o = 16; o; o >>= 1) acc += __shfl_xor_sync(0xffffffffu, acc, o);
                if (lane == 0) s_lg[v] = acc + b_proj[v];
            }
            __syncthreads();
            if (rank == 0 && tid < NV)
                out[(size_t)s * (BB * NV) + b * NV + tid] = s_lg[tid];
            if (tid == 0) {
                int am = 0; float mv = s_lg[0];
                for (int v = 1; v < NV; ++v) if (s_lg[v] > mv) { mv = s_lg[v]; am = v; }
                s_chr[0] = am;
                if (rank == 0 && write_preds)
                    out[(size_t)STEPS * BB * NV + (size_t)s * BB + b] = (float)am;
            }
        }
        if (s == STEPS - 1) break;

        // ================= attend(h_new): own t-half ======================
        for (int q = wid; q < KD; q += 16) {
            float acc = 0.f;
            const float* wr = W_phi + (size_t)q * HD;
            for (int k = lane; k < HD; k += 32) acc += s_h[k] * wr[k];
            #pragma unroll
            for (int o = 16; o; o >>= 1) acc += __shfl_xor_sync(0xffffffffu, acc, o);
            if (lane == 0) s_q[q] = acc + b_phi[q];
        }
        __syncthreads();

        const long gbase = (long)(s + 1) * CPS;

        // ---- energy: 16 key chunks (8 k-rows x 2KB); t = 2tid, 2tid+1
        float e0 = 0.f, e1 = 0.f;
        for (int ci = 0; ci < 16; ci++) {
            long gc = gbase + ci;
            int st = (int)(gc % NS);
            unsigned par = (unsigned)((gc / NS) & 1);
            if (lane == 0) mbar_wait(mbF + st * 8, par);
            __syncwarp();
            const __half2* buf = (const __half2*)(dsm + RING_OFF + st * CH);
            #pragma unroll
            for (int r = 0; r < 8; r++) {
                float2 kv = __half22float2(buf[r * 512 + tid]);
                float q = s_q[ci * 8 + r];
                e0 += q * kv.x;
                e1 += q * kv.y;
            }
            __syncwarp();
            if (lane == 0) mbar_arrive(mbE + st * 8);
            if (tid == 0) {
                long nc = gc + NS;
                if (nc < TOTC) {
                    mbar_wait(mbE + st * 8, par);
                    int idx = (int)(nc % CPS);
                    const char* src = (idx < 16) ? (kbase + (size_t)idx * CH)
                                                 : (vbase + (size_t)(idx - 16) * CH);
                    mbar_expect_tx(mbF + st * 8, CH);
                    tma_ld(ring0 + st * CH, src, CH, mbF + st * 8);
                }
            }
        }
        __syncthreads();

        // ---- local softmax stats (m_r, s_r), cluster merge
        {
            float m = fmaxf(e0, e1);
            #pragma unroll
            for (int o = 16; o; o >>= 1) m = fmaxf(m, __shfl_xor_sync(0xffffffffu, m, o));
            if (lane == 0) s_red[wid] = m;
        }
        __syncthreads();
        if (wid == 0) {
            float v = (lane < 16) ? s_red[lane] : -1e30f;
            #pragma unroll
            for (int o = 8; o; o >>= 1) v = fmaxf(v, __shfl_xor_sync(0xffffffffu, v, o));
            if (lane == 0) s_ms[0] = v;
        }
        __syncthreads();
        {
            float mr = s_ms[0];
            float w0 = __expf(e0 - mr), w1 = __expf(e1 - mr);
            ((float2*)w_s)[tid] = make_float2(w0, w1);
            float ls = w0 + w1;
            #pragma unroll
            for (int o = 16; o; o >>= 1) ls += __shfl_xor_sync(0xffffffffu, ls, o);
            if (lane == 0) s_red[wid] = ls;
        }
        __syncthreads();
        if (wid == 0) {
            float v = (lane < 16) ? s_red[lane] : 0.f;
            #pragma unroll
            for (int o = 8; o; o >>= 1) v += __shfl_xor_sync(0xffffffffu, v, o);
            if (lane == 0) {
                s_ms[1] = v;
                unsigned pa = mapa_rank(a_ms, pr);
                stsc_f(pa + 2 * 4, s_ms[0]);
                stsc_f(pa + 3 * 4, v);
            }
        }
        __syncthreads();
        CLUSTER_SYNC();    // (2) (m,s) exchanged

        float M  = fmaxf(s_ms[0], s_ms[2]);
        float fo = __expf(s_ms[0] - M);
        float S  = s_ms[1] * fo + s_ms[3] * __expf(s_ms[2] - M);

        // ---- values: 16 chunks (64 t-rows x 256B)
        {
            int kc = tid & 15, tg = tid >> 4;
            float va[8];
            #pragma unroll
            for (int j = 0; j < 8; j++) va[j] = 0.f;
            for (int ci = 0; ci < 16; ci++) {
                long gc = gbase + 16 + ci;
                int st = (int)(gc % NS);
                unsigned par = (unsigned)((gc / NS) & 1);
                if (lane == 0) mbar_wait(mbF + st * 8, par);
                __syncwarp();
                const char* buf = dsm + RING_OFF + st * CH;
                #pragma unroll
                for (int j = 0; j < 2; j++) {
                    int row = tg + 32 * j;
                    U4 vv; vv.u = *(const uint4*)(buf + row * 256 + kc * 16);
                    float w = w_s[ci * 64 + row];
                    float2 f0 = __half22float2(vv.h[0]);
                    float2 f1 = __half22float2(vv.h[1]);
                    float2 f2 = __half22float2(vv.h[2]);
                    float2 f3 = __half22float2(vv.h[3]);
                    va[0] += w * f0.x; va[1] += w * f0.y;
                    va[2] += w * f1.x; va[3] += w * f1.y;
                    va[4] += w * f2.x; va[5] += w * f2.y;
                    va[6] += w * f3.x; va[7] += w * f3.y;
                }
                __syncwarp();
                if (lane == 0) mbar_arrive(mbE + st * 8);
                if (tid == 0) {
                    long nc = gc + NS;
                    if (nc < TOTC) {
                        mbar_wait(mbE + st * 8, par);
                        int idx = (int)(nc % CPS);
                        const char* src = (idx < 16) ? (kbase + (size_t)idx * CH)
                                                     : (vbase + (size_t)(idx - 16) * CH);
                        mbar_expect_tx(mbF + st * 8, CH);
                        tma_ld(ring0 + st * CH, src, CH, mbF + st * 8);
                    }
                }
            }
            #pragma unroll
            for (int j = 0; j < 8; j++)
                va[j] += __shfl_xor_sync(0xffffffffu, va[j], 16);
            if ((lane >> 4) == 0) {
                float4* cp = (float4*)(scr + wid * 128 + kc * 8);
                cp[0] = make_float4(va[0], va[1], va[2], va[3]);
                cp[1] = make_float4(va[4], va[5], va[6], va[7]);
            }
        }
        __syncthreads();

        // ---- ctx partial (scaled by exp(m_r - M)), exchange, combine
        if (tid < 128) {
            float acc = 0.f;
            #pragma unroll
            for (int w = 0; w < 16; w++) acc += scr[w * 128 + tid];
            acc *= fo;
            scr[tid] = acc;        // stash own scaled partial
            stsc_f(mapa_rank(a_cxp, pr) + tid * 4, acc);
        }
        __syncthreads();
        CLUSTER_SYNC();    // (3) ctx partials exchanged

        if (tid < 128) s_x[tid] = (scr[tid] + s_cxp[tid]) / S;
        for (int i = tid; i < HD; i += NTHR) s_x[128 + i] = s_h[i];
        __syncthreads();
    }
}

// ---------------- host launcher ----------------
extern "C" void kernel_launch(void* const* d_in, const int* in_sizes, int n_in,
                              void* d_out, int out_size) {
    const float* keys   = (const float*)d_in[0];
    const float* values = (const float*)d_in[1];
    const float* emb    = (const float*)d_in[2];
    const float* W_phi  = (const float*)d_in[3];
    const float* b_phi  = (const float*)d_in[4];
    const float* W_ih   = (const float*)d_in[5];
    const float* b_ih   = (const float*)d_in[6];
    const float* W_hh   = (const float*)d_in[7];
    const float* b_hh   = (const float*)d_in[8];
    const float* W_proj = (const float*)d_in[9];
    const float* b_proj = (const float*)d_in[10];
    const float* h0     = (const float*)d_in[11];
    const float* c0     = (const float*)d_in[12];
    float* out = (float*)d_out;

    int write_preds = (out_size >= STEPS * BB * NV + STEPS * BB) ? 1 : 0;

    static int attr_done = 0;
    if (!attr_done) {
        cudaFuncSetAttribute(decoder_persistent,
                             cudaFuncAttributeMaxDynamicSharedMemorySize,
                             SMEM_BYTES);
        attr_done = 1;
    }

    init_kernel<<<NV + TRB + KTB + WQB, 256>>>(keys, values, emb, W_ih, b_ih,
                                               b_hh, W_hh);
    decoder_persistent<<<BB * 2, NTHR, SMEM_BYTES>>>(W_phi, b_phi, W_proj,
                                                     b_proj, h0, c0, out,
                                                     write_preds);
}